// round 16
// baseline (speedup 1.0000x reference)
#include <cuda_runtime.h>
#include <cuda_bf16.h>
#include <math.h>
#include <stdint.h>

#define Hd 128
#define Ed 32
#define Ld 256
#define Bd 8
#define NROW (Bd*Ld)

// ---------- helpers ----------
__device__ __forceinline__ uint32_t smem_u32(const void* p){
    uint32_t a;
    asm("{ .reg .u64 t; cvta.to.shared.u64 t, %1; cvt.u32.u64 %0, t; }" : "=r"(a) : "l"(p));
    return a;
}
__device__ __forceinline__ void ldsm4(uint32_t& r0,uint32_t& r1,uint32_t& r2,uint32_t& r3,uint32_t a){
    asm volatile("ldmatrix.sync.aligned.m8n8.x4.shared.b16 {%0,%1,%2,%3}, [%4];"
        : "=r"(r0),"=r"(r1),"=r"(r2),"=r"(r3) : "r"(a));
}
__device__ __forceinline__ void mma16816(float* c, const uint32_t* a, const uint32_t* b){
    asm volatile("mma.sync.aligned.m16n8k16.row.col.f32.bf16.bf16.f32 "
        "{%0,%1,%2,%3}, {%4,%5,%6,%7}, {%8,%9}, {%0,%1,%2,%3};"
        : "+f"(c[0]),"+f"(c[1]),"+f"(c[2]),"+f"(c[3])
        : "r"(a[0]),"r"(a[1]),"r"(a[2]),"r"(a[3]), "r"(b[0]),"r"(b[1]));
}
__device__ __forceinline__ float tanh_fast(float x){
    float y; asm("tanh.approx.f32 %0, %1;" : "=f"(y) : "f"(x)); return y;
}
__device__ __forceinline__ unsigned short bf16raw(float x){
    __nv_bfloat16 b = __float2bfloat16(x);
    return *reinterpret_cast<unsigned short*>(&b);
}
__device__ __forceinline__ float bf16val(unsigned short u){
    __nv_bfloat16 b = *reinterpret_cast<__nv_bfloat16*>(&u);
    return __bfloat162float(b);
}
// fast 2-way split: hi = truncated-bf16 pair (pure byte-perm), lo = rn-bf16 of residual
__device__ __forceinline__ void split2(float v0, float v1, uint32_t& hi, uint32_t& lo){
    uint32_t u0 = __float_as_uint(v0), u1 = __float_as_uint(v1);
    hi = __byte_perm(u0, u1, 0x7632);
    float h0 = __uint_as_float(u0 & 0xFFFF0000u);
    float h1 = __uint_as_float(u1 & 0xFFFF0000u);
    asm("cvt.rn.bf16x2.f32 %0, %1, %2;" : "=r"(lo) : "f"(v1 - h1), "f"(v0 - h0));
}
// swizzled byte offset, 256B-stride tile (A): row r, byte col c2 (<256)
__device__ __forceinline__ uint32_t sw(int r, int c2){
    return (uint32_t)(r*256 + (c2 ^ ((r & 7) << 4)));
}
#define CP_ASYNC16(dst, src) asm volatile("cp.async.ca.shared.global [%0], [%1], 16;" :: "r"(dst), "l"(src))
#define CP_COMMIT()          asm volatile("cp.async.commit_group;" ::: "memory")
#define CP_WAIT0()           asm volatile("cp.async.wait_group 0;" ::: "memory")

// ---------- scratch ----------
__device__ float g_asrc[NROW*Hd];
__device__ float g_adst[NROW*Hd];
__device__ float g_hWm[NROW*Hd];
__device__ float g_V[NROW*4*Hd];
__device__ float g_S[NROW*4];
__device__ unsigned char g_mask[NROW];
__device__ int g_jcnt[Bd];
__device__ int g_jidx[Bd][Ld];
// weights packed as the exact smem image: [half(2)][hi 16KB | lo 16KB], rows n (128B stride,
// swizzled). [0]=We1 (half0 only), [1]=We2, [2]=Wae, [3]=Wme
__device__ __align__(16) unsigned short g_W[4][32768];

// ---------- setup body (256 threads): mask canonicalize + j-compaction ----------
__device__ void setup_body(const unsigned char* __restrict__ p, int t, int* sInts /* >= 10 */)
{
    int* fF = sInts; int* fB = sInts + 1; int* wcnt = sInts + 2;   // wcnt[8]
    int wid = t >> 5, lane = t & 31;
    if (t == 0) { *fF = 0; *fB = 0; }
    __syncthreads();
    for (int i = t; i < NROW; i += 256) {
        unsigned char v = p[i];
        if (v > 1) atomicOr(fF, 1);
        else if (v != 0 && (i & 3) != 0) atomicOr(fB, 1);
    }
    __syncthreads();
    bool isF = *fF != 0, isB = *fB != 0;
    for (int r = t; r < NROW; r += 256) {
        unsigned char m;
        if (isF)      m = (((const float*)p)[r] != 0.f) ? 1 : 0;
        else if (isB) m = p[r] ? 1 : 0;
        else          m = p[4*r] ? 1 : 0;
        g_mask[r] = m;
    }
    __syncthreads();
    for (int b = 0; b < Bd; b++) {
        int valid = (g_mask[b*Ld + t] != 0) ? 1 : 0;
        unsigned bal = __ballot_sync(0xffffffffu, valid);
        if (lane == 0) wcnt[wid] = __popc(bal);
        __syncthreads();
        int off = 0;
        #pragma unroll
        for (int w = 0; w < 8; w++) if (w < wid) off += wcnt[w];
        int pre = __popc(bal & ((1u << lane) - 1u));
        if (valid) g_jidx[b][off + pre] = t;
        if (t == 0) {
            int tot = 0;
            #pragma unroll
            for (int w = 0; w < 8; w++) tot += wcnt[w];
            g_jcnt[b] = tot;
        }
        __syncthreads();
    }
}

// ---------- kernel 1: k-split precompute + weight prep + setup (fused, 256 thr) ----------
__global__ void __launch_bounds__(256)
prep_kernel(const float* __restrict__ h, const unsigned char* __restrict__ maskraw,
            const float* __restrict__ We1, const float* __restrict__ We2,
            const float* __restrict__ Wa1, const float* __restrict__ Wm1)
{
    __shared__ float sh[16][Hd];
    __shared__ float sPart[2][16][Hd];
    __shared__ int sInts[10];
    int t = threadIdx.x;   // 256
    if (blockIdx.x < NROW/16) {
        // ---- precompute: 16 rows, k-split halves ----
        int r0 = blockIdx.x * 16;
        int n = t & 127, kh = t >> 7;
        const int kb = kh * 64;
        for (int i = t; i < 16*Hd; i += 256) {
            int r = i >> 7, c = i & 127;
            sh[r][c] = h[(r0 + r)*Hd + c];
        }
        __syncthreads();
        float acc[16];
        // pass 1: asrc = h @ Wa1[:H]
        #pragma unroll
        for (int r = 0; r < 16; r++) acc[r] = 0.f;
        #pragma unroll 8
        for (int k = kb; k < kb + 64; k++) {
            float wv = __ldg(&Wa1[k*Hd + n]);
            #pragma unroll
            for (int r = 0; r < 16; r++) acc[r] = fmaf(sh[r][k], wv, acc[r]);
        }
        #pragma unroll
        for (int r = 0; r < 16; r++) sPart[kh][r][n] = acc[r];
        __syncthreads();
        #pragma unroll
        for (int rr = 0; rr < 8; rr++) {
            int r = kh*8 + rr;
            g_asrc[(size_t)(r0 + r)*Hd + n] = sPart[0][r][n] + sPart[1][r][n];
        }
        __syncthreads();
        // pass 2: adst = h @ Wa1[H:2H]
        #pragma unroll
        for (int r = 0; r < 16; r++) acc[r] = 0.f;
        #pragma unroll 8
        for (int k = kb; k < kb + 64; k++) {
            float wv = __ldg(&Wa1[(Hd + k)*Hd + n]);
            #pragma unroll
            for (int r = 0; r < 16; r++) acc[r] = fmaf(sh[r][k], wv, acc[r]);
        }
        #pragma unroll
        for (int r = 0; r < 16; r++) sPart[kh][r][n] = acc[r];
        __syncthreads();
        #pragma unroll
        for (int rr = 0; rr < 8; rr++) {
            int r = kh*8 + rr;
            g_adst[(size_t)(r0 + r)*Hd + n] = sPart[0][r][n] + sPart[1][r][n];
        }
        __syncthreads();
        // pass 3: hWm = h @ Wm1[:H]
        #pragma unroll
        for (int r = 0; r < 16; r++) acc[r] = 0.f;
        #pragma unroll 8
        for (int k = kb; k < kb + 64; k++) {
            float wv = __ldg(&Wm1[k*Hd + n]);
            #pragma unroll
            for (int r = 0; r < 16; r++) acc[r] = fmaf(sh[r][k], wv, acc[r]);
        }
        #pragma unroll
        for (int r = 0; r < 16; r++) sPart[kh][r][n] = acc[r];
        __syncthreads();
        #pragma unroll
        for (int rr = 0; rr < 8; rr++) {
            int r = kh*8 + rr;
            g_hWm[(size_t)(r0 + r)*Hd + n] = sPart[0][r][n] + sPart[1][r][n];
        }
    } else if (blockIdx.x < NROW/16 + Hd/2) {
        // ---- weight transpose+split+swizzle: 2 n-rows per block ----
        int n = (blockIdx.x - NROW/16)*2 + (t >> 7), k = t & 127;
        int half = k >> 6, kp = k & 63;
        uint32_t idx = (uint32_t)half*16384u + (uint32_t)n*64u
                     + ((((uint32_t)(kp*2)) ^ (uint32_t)((n & 7) << 4)) >> 1);
        if (k < Ed) {
            float w = We1[k*Hd + n];
            unsigned short hh = bf16raw(w);
            g_W[0][idx] = hh; g_W[0][idx + 8192] = bf16raw(w - bf16val(hh));
        }
        { float w = We2[k*Hd + n];        unsigned short hh=bf16raw(w); g_W[1][idx]=hh; g_W[1][idx+8192]=bf16raw(w-bf16val(hh)); }
        { float w = Wa1[(2*Hd+k)*Hd + n]; unsigned short hh=bf16raw(w); g_W[2][idx]=hh; g_W[2][idx+8192]=bf16raw(w-bf16val(hh)); }
        { float w = Wm1[(Hd+k)*Hd + n];   unsigned short hh=bf16raw(w); g_W[3][idx]=hh; g_W[3][idx+8192]=bf16raw(w-bf16val(hh)); }
    } else {
        setup_body(maskraw, t, sInts);
    }
}

// ---------- edge kernel smem layout (bytes) ----------
#define OFF_VECA 0
#define OFF_VECM 512
#define OFF_WA2  1024
#define OFF_BE1  1536
#define OFF_BE2  2048
#define OFF_SW   2560
#define OFF_RED  2816
#define OFF_VAGG 3328
#define OFF_JIDX 3840
#define OFF_AHI  4096
#define OFF_ALO  (OFF_AHI + 16384)
#define OFF_B0   (OFF_ALO + 16384)    // 32 KB: one K-half (hi 16K | lo 16K)
#define OFF_B1   (OFF_B0 + 32768)
#define SMEM_TOTAL (OFF_B1 + 32768)   // 102400

// async-copy one 32 KB weight K-half into a B buffer
__device__ __forceinline__ void cpasyncB(uint32_t dst, const unsigned short* src, int tid){
    const char* s = (const char*)src;
    #pragma unroll
    for (int i = 0; i < 16; i++) {
        int x = (tid + i*128) * 16;
        CP_ASYNC16(dst + (uint32_t)x, s + x);
    }
    CP_COMMIT();
}

// 3-pass bf16-split GEMM over one K-half. A: 256B-stride swizzled (full K=128);
// B: 128B-stride swizzled half-buffer, hi at bB, lo at bB+16384. kA0 = A k-elem offset.
template<int KS>
__device__ __forceinline__ void gemm_half(float C[2][8][4],
                                          uint32_t aHi, uint32_t aLo, uint32_t bB,
                                          int m0, int n0, int lane, int kA0)
{
    const int ra = m0 + (lane & 15);
    const uint32_t abase = (uint32_t)ra*256, axor = (uint32_t)((ra & 7) << 4);
    const int ac0 = (lane >> 4) * 16;
    const int rb = n0 + (lane & 7) + ((lane & 16) ? 8 : 0);
    const uint32_t bbase = (uint32_t)rb*128, bxor = (uint32_t)((rb & 7) << 4);
    const int bc0 = (lane & 8) ? 16 : 0;
    #pragma unroll
    for (int ks = 0; ks < KS; ks++) {
        const uint32_t ao = (uint32_t)(ac0 + kA0*2 + ks*32) ^ axor;
        const uint32_t bo = (uint32_t)(bc0 + ks*32) ^ bxor;
        uint32_t aH[2][4], aL[2][4], bH[8][2], bL[8][2];
        #pragma unroll
        for (int im = 0; im < 2; im++) {
            uint32_t ad = abase + (uint32_t)(im*16*256) + ao;
            ldsm4(aH[im][0],aH[im][1],aH[im][2],aH[im][3], aHi + ad);
            ldsm4(aL[im][0],aL[im][1],aL[im][2],aL[im][3], aLo + ad);
        }
        #pragma unroll
        for (int ib = 0; ib < 4; ib++) {
            uint32_t bd = bbase + (uint32_t)(ib*16*128) + bo;
            ldsm4(bH[2*ib][0],bH[2*ib][1],bH[2*ib+1][0],bH[2*ib+1][1], bB + bd);
            ldsm4(bL[2*ib][0],bL[2*ib][1],bL[2*ib+1][0],bL[2*ib+1][1], bB + 16384 + bd);
        }
        #pragma unroll
        for (int im = 0; im < 2; im++)
            #pragma unroll
            for (int in = 0; in < 8; in++) {
                mma16816(C[im][in], aH[im], bH[in]);
                mma16816(C[im][in], aH[im], bL[in]);
                mma16816(C[im][in], aL[im], bH[in]);
            }
    }
}

#define ZC() { _Pragma("unroll") for(int _i=0;_i<2;_i++) _Pragma("unroll") for(int _j=0;_j<8;_j++) _Pragma("unroll") for(int _k=0;_k<4;_k++) C[_i][_j][_k]=0.f; }

// epilogue: bias (+relu), split to bf16 hi/lo (truncation trick), store into A tiles
__device__ __forceinline__ void epi_store_A(float C[2][8][4], const float* __restrict__ bias,
                                            bool do_relu, unsigned char* smem,
                                            int m0, int n0, int lane)
{
    #pragma unroll
    for (int im = 0; im < 2; im++)
        #pragma unroll
        for (int in = 0; in < 8; in++) {
            int n = n0 + in*8 + 2*(lane & 3);
            float b0 = bias[n], b1 = bias[n+1];
            #pragma unroll
            for (int hh = 0; hh < 2; hh++) {
                int m = m0 + im*16 + hh*8 + (lane >> 2);
                float v0 = C[im][in][2*hh]   + b0;
                float v1 = C[im][in][2*hh+1] + b1;
                if (do_relu) { v0 = fmaxf(v0, 0.f); v1 = fmaxf(v1, 0.f); }
                uint32_t hi, lo;
                split2(v0, v1, hi, lo);
                uint32_t off = sw(m, n*2);
                *(uint32_t*)(smem + OFF_AHI + off) = hi;
                *(uint32_t*)(smem + OFF_ALO + off) = lo;
            }
        }
}

// block: (jt, i, b) -> 64 compacted j's (jidx[j0..j0+63]) of row (b,i); M=64, N=128
__global__ void __launch_bounds__(128, 2)
edge_kernel(const float* __restrict__ ef,
            const float* __restrict__ be1, const float* __restrict__ be2,
            const float* __restrict__ ba1, const float* __restrict__ ba2,
            const float* __restrict__ Wa2, const float* __restrict__ bm1)
{
    extern __shared__ unsigned char smem[];
    const uint32_t sb = smem_u32(smem);
    const int tid = threadIdx.x, lane = tid & 31, wid = tid >> 5;
    const int wm = wid >> 1, wn = wid & 1;
    const int m0 = wm*32, n0 = wn*64;
    const int jt = blockIdx.x, i = blockIdx.y, b = blockIdx.z;
    const int row = b*Ld + i;
    const int j0  = jt*64;
    const int cnt = g_jcnt[b];

    // ---- early exit: masked center row, or j-tile beyond valid count (no writes) ----
    if (g_mask[row] == 0 || j0 >= cnt) return;

    float* sVA  = (float*)(smem + OFF_VECA);
    float* sVM  = (float*)(smem + OFF_VECM);
    float* sW2  = (float*)(smem + OFF_WA2);
    float* sB1  = (float*)(smem + OFF_BE1);
    float* sB2  = (float*)(smem + OFF_BE2);
    float* swv  = (float*)(smem + OFF_SW);
    float* red  = (float*)(smem + OFF_RED);
    float* sVag = (float*)(smem + OFF_VAGG);
    int*   sJ   = (int*)(smem + OFF_JIDX);
    const uint32_t aHi = sb + OFF_AHI, aLo = sb + OFF_ALO;
    const uint32_t B0 = sb + OFF_B0, B1 = sb + OFF_B1;

    // prefetch We1 half0 immediately (overlaps all scalar staging below)
    cpasyncB(B0, g_W[0], tid);

    sVA[tid] = g_asrc[row*Hd + tid] + __ldg(&ba1[tid]);
    sVM[tid] = g_hWm [row*Hd + tid] + __ldg(&bm1[tid]);
    sW2[tid] = __ldg(&Wa2[tid]);
    sB1[tid] = __ldg(&be1[tid]);
    sB2[tid] = __ldg(&be2[tid]);
    sVag[tid] = 0.f;
    if (tid < 64) {
        int jj = j0 + tid;
        sJ[tid] = (jj < cnt) ? g_jidx[b][jj] : g_jidx[b][0];
    }

    // stage EF (64 gathered rows x 32) split hi/lo into A tiles
    {
        int r = tid >> 1, half = tid & 1;
        int jj = j0 + r;
        int jv = (jj < cnt) ? __ldg(&g_jidx[b][jj]) : __ldg(&g_jidx[b][0]);
        const float* src = ef + (((size_t)row*Ld) + jv)*Ed + half*16;
        uint32_t hi[8], lo[8];
        #pragma unroll
        for (int g = 0; g < 4; g++) {
            float4 v = *(const float4*)(src + g*4);
            split2(v.x, v.y, hi[2*g],   lo[2*g]);
            split2(v.z, v.w, hi[2*g+1], lo[2*g+1]);
        }
        uint32_t o0 = sw(r, half*32), o1 = sw(r, half*32 + 16);
        *(uint4*)(smem + OFF_AHI + o0) = make_uint4(hi[0],hi[1],hi[2],hi[3]);
        *(uint4*)(smem + OFF_AHI + o1) = make_uint4(hi[4],hi[5],hi[6],hi[7]);
        *(uint4*)(smem + OFF_ALO + o0) = make_uint4(lo[0],lo[1],lo[2],lo[3]);
        *(uint4*)(smem + OFF_ALO + o1) = make_uint4(lo[4],lo[5],lo[6],lo[7]);
    }
    CP_WAIT0();
    __syncthreads();

    float C[2][8][4];

    // ---- G1: T = relu(EF @ We1 + be1) (K=32, B0) ----
    ZC();
    gemm_half<2>(C, aHi, aLo, B0, m0, n0, lane, 0);
    cpasyncB(B1, g_W[1], tid);                 // We2 h0 -> B1 (B1 unused yet)
    __syncthreads();                           // all warps done reading A (G1)
    epi_store_A(C, sB1, true, smem, m0, n0, lane);
    CP_WAIT0();
    __syncthreads();                           // T visible + B1 ready

    // ---- G2: EH = T @ We2 + be2 (two K-halves) ----
    ZC();
    gemm_half<4>(C, aHi, aLo, B1, m0, n0, lane, 0);
    cpasyncB(B0, g_W[1] + 16384, tid);         // We2 h1 -> B0 (B0 free since pre-epi sync)
    CP_WAIT0();
    __syncthreads();                           // B0 ready; all warps done with B1
    gemm_half<4>(C, aHi, aLo, B0, m0, n0, lane, 64);
    cpasyncB(B1, g_W[2], tid);                 // Wae h0 -> B1
    __syncthreads();                           // all warps done reading A (G2)
    epi_store_A(C, sB2, false, smem, m0, n0, lane);
    CP_WAIT0();
    __syncthreads();                           // EH visible + B1 ready

    // ---- G3a: U = EH @ Wae ----
    ZC();
    gemm_half<4>(C, aHi, aLo, B1, m0, n0, lane, 0);
    cpasyncB(B0, g_W[2] + 16384, tid);         // Wae h1 -> B0
    CP_WAIT0();
    __syncthreads();
    gemm_half<4>(C, aHi, aLo, B0, m0, n0, lane, 64);
    cpasyncB(B1, g_W[3], tid);                 // Wme h0 -> B1
    // attention epilogue (C regs are this thread's; no sync needed before use)
    {
        #pragma unroll
        for (int im = 0; im < 2; im++)
            #pragma unroll
            for (int hh = 0; hh < 2; hh++) {
                int m = m0 + im*16 + hh*8 + (lane >> 2);
                const float* ad = g_adst + (((size_t)b*Ld) + sJ[m])*Hd;
                float part = 0.f;
                #pragma unroll
                for (int in = 0; in < 8; in++) {
                    int n = n0 + in*8 + 2*(lane & 3);
                    float2 a2 = *(const float2*)(ad + n);
                    float u0 = C[im][in][2*hh]   + sVA[n]   + a2.x;
                    float u1 = C[im][in][2*hh+1] + sVA[n+1] + a2.y;
                    part = fmaf(tanh_fast(u0), sW2[n],   part);
                    part = fmaf(tanh_fast(u1), sW2[n+1], part);
                }
                part += __shfl_xor_sync(0xffffffffu, part, 1);
                part += __shfl_xor_sync(0xffffffffu, part, 2);
                if ((lane & 3) == 0) red[m*2 + wn] = part;
            }
    }
    __syncthreads();
    if (tid < 64) {
        float s = red[tid*2] + red[tid*2 + 1];
        float logit = (s + __ldg(&ba2[0])) * 0.08838834764831845f;
        bool valid = (j0 + tid) < cnt;         // compacted j's are all mask-valid
        swv[tid] = valid ? __expf(logit) : 0.f;
    }
    CP_WAIT0();
    __syncthreads();                           // B1 (Wme h0) ready + swv visible

    // ---- G3b: MPpre = EH @ Wme ----
    ZC();
    gemm_half<4>(C, aHi, aLo, B1, m0, n0, lane, 0);
    cpasyncB(B0, g_W[3] + 16384, tid);         // Wme h1 -> B0
    CP_WAIT0();
    __syncthreads();
    gemm_half<4>(C, aHi, aLo, B0, m0, n0, lane, 64);
    // message epilogue + weighted aggregation
    {
        float vacc[8][2];
        #pragma unroll
        for (int in = 0; in < 8; in++) { vacc[in][0] = 0.f; vacc[in][1] = 0.f; }
        #pragma unroll
        for (int im = 0; im < 2; im++)
            #pragma unroll
            for (int hh = 0; hh < 2; hh++) {
                int m = m0 + im*16 + hh*8 + (lane >> 2);
                float w = swv[m];
                #pragma unroll
                for (int in = 0; in < 8; in++) {
                    int n = n0 + in*8 + 2*(lane & 3);
                    vacc[in][0] = fmaf(w, fmaxf(C[im][in][2*hh]   + sVM[n],   0.f), vacc[in][0]);
                    vacc[in][1] = fmaf(w, fmaxf(C[im][in][2*hh+1] + sVM[n+1], 0.f), vacc[in][1]);
                }
            }
        #pragma unroll
        for (int in = 0; in < 8; in++)
            #pragma unroll
            for (int c = 0; c < 2; c++) {
                float v = vacc[in][c];
                v += __shfl_xor_sync(0xffffffffu, v, 4);
                v += __shfl_xor_sync(0xffffffffu, v, 8);
                v += __shfl_xor_sync(0xffffffffu, v, 16);
                if (lane < 4) atomicAdd(&sVag[n0 + in*8 + 2*lane + c], v);
            }
    }
    __syncthreads();
    g_V[((size_t)row*4 + jt)*Hd + tid] = sVag[tid];
    if (tid < 64) {
        float wv = swv[tid];
        #pragma unroll
        for (int o = 16; o > 0; o >>= 1) wv += __shfl_xor_sync(0xffffffffu, wv, o);
        if ((tid & 31) == 0) red[tid >> 5] = wv;
    }
    __syncthreads();
    if (tid == 0) g_S[row*4 + jt] = red[0] + red[1];
}

// ---------- final kernel v3: 16 rows/block, 256 threads, k-split halves ----------
__global__ void __launch_bounds__(256)
final_kernel(const float* __restrict__ h,
             const float* __restrict__ Wm2, const float* __restrict__ bm2,
             const float* __restrict__ Wo1, const float* __restrict__ bo1,
             const float* __restrict__ Wo2, const float* __restrict__ bo2,
             const float* __restrict__ gamma, const float* __restrict__ beta,
             float* __restrict__ out)
{
    int t = threadIdx.x;
    int n = t & 127, kh = t >> 7;        // kh in {0,1}; k range [kh*64, kh*64+64)
    int r0 = blockIdx.x * 16;            // 128 blocks
    int b = r0 >> 8;
    __shared__ float sA[16][Hd];         // agg; reused as sP after stage 1
    __shared__ float sH[16][Hd];
    __shared__ float sX2[16][Hd];
    __shared__ float sPart[2][16][Hd];
    __shared__ float sMu[16], sRs[16];
    float* sP = &sA[0][0];               // alias: sA dead after stage-1 partials

    int cnt = g_jcnt[b];
    int ntiles = (cnt + 63) >> 6;
    for (int i = t; i < 16*Hd; i += 256) {
        int r = i >> 7, c = i & 127;
        int row = r0 + r;
        sH[r][c] = h[row*Hd + c];
        float a = 0.f;
        if (g_mask[row]) {
            float v = 0.f, S = 0.f;
            for (int jt = 0; jt < ntiles; jt++) {
                v += g_V[((size_t)row*4 + jt)*Hd + c];
                S += g_S[row*4 + jt];
            }
            a = v / S;
        }
        sA[r][c] = a;
    }
    __syncthreads();

    float acc[16];
    const int kb = kh*64;
    // ---- stage 1: X2 = agg @ Wm2 + bm2 ----
    #pragma unroll
    for (int r = 0; r < 16; r++) acc[r] = 0.f;
    #pragma unroll 8
    for (int k = kb; k < kb + 64; k++) {
        float wv = __ldg(&Wm2[k*Hd + n]);
        #pragma unroll
        for (int r = 0; r < 16; r++) acc[r] = fmaf(sA[r][k], wv, acc[r]);
    }
    #pragma unroll
    for (int r = 0; r < 16; r++) sPart[kh][r][n] = acc[r];
    __syncthreads();
    {
        float bm = __ldg(&bm2[n]);
        #pragma unroll
        for (int rr = 0; rr < 8; rr++) {
            int r = kh*8 + rr;
            sX2[r][n] = bm + sPart[0][r][n] + sPart[1][r][n];
        }
    }
    __syncthreads();
    // ---- stage 2: P = relu(h@Wo1[:H] + X2@Wo1[H:] + bo1)  (sP aliases sA) ----
    #pragma unroll
    for (int r = 0; r < 16; r++) acc[r] = 0.f;
    #pragma unroll 4
    for (int k = kb; k < kb + 64; k++) {
        float w1 = __ldg(&Wo1[k*Hd + n]);
        float w2 = __ldg(&Wo1[(Hd + k)*Hd + n]);
        #pragma unroll
        for (int r = 0; r < 16; r++) {
            acc[r] = fmaf(sH[r][k],  w1, acc[r]);
            acc[r] = fmaf(sX2[r][k], w2, acc[r]);
        }
    }
    __syncthreads();                      // all reads of sA (stage-1 operand) complete
    #pragma unroll
    for (int r = 0; r < 16; r++) sPart[kh][r][n] = acc[r];
    __syncthreads();
    {
        float b1 = __ldg(&bo1[n]);
        #pragma unroll
        for (int rr = 0; rr < 8; rr++) {
            int r = kh*8 + rr;
            sP[r*Hd + n] = fmaxf(b1 + sPart[0][r][n] + sPart[1][r][n], 0.f);
        }
    }
    __syncthreads();
    // ---- stage 3: res = h + P@Wo2 + bo2 -> sX2 ----
    #pragma unroll
    for (int r = 0; r < 16; r++) acc[r] = 0.f;
    #pragma unroll 8
    for (int k = kb; k < kb + 64; k++) {
        float wv = __ldg(&Wo2[k*Hd + n]);
        #pragma unroll
        for (int r = 0; r < 16; r++) acc[r] = fmaf(sP[r*Hd + k], wv, acc[r]);
    }
    #pragma unroll
    for (int r = 0; r < 16; r++) sPart[kh][r][n] = acc[r];
    __syncthreads();
    {
        float b2 = __ldg(&bo2[n]);
        #pragma unroll
        for (int rr = 0; rr < 8; rr++) {
            int r = kh*8 + rr;
            sX2[r][n] = sH[r][n] + b2 + sPart[0][r][n] + sPart[1][r][n];
        }
    }
    __syncthreads();
    // ---- LayerNorm: 8 warps, 2 rows each ----
    {
        int w = t >> 5, lane = t & 31;
        #pragma unroll
        for (int g = 0; g < 2; g++) {
            int r = w*2 + g;
            float s = 0.f, q = 0.f;
            #pragma unroll
            for (int x = 0; x < 4; x++) {
                float v = sX2[r][lane + x*32];
                s += v; q = fmaf(v, v, q);
            }
            #pragma unroll
            for (int o = 16; o > 0; o >>= 1) {
                s += __shfl_xor_sync(0xffffffffu, s, o);
                q += __shfl_xor_sync(0xffffffffu, q, o);
            }
            if (lane == 0) {
                float mu = s * (1.f/128.f);
                float var = q * (1.f/128.f) - mu*mu;
                sMu[r] = mu; sRs[r] = rsqrtf(var + 1e-5f);
            }
        }
    }
    __syncthreads();
    for (int i = t; i < 16*Hd; i += 256) {
        int r = i >> 7, c = i & 127;
        int row = r0 + r;
        float o = (sX2[r][c] - sMu[r]) * sRs[r] * __ldg(&gamma[c]) + __ldg(&beta[c]);
        out[row*Hd + c] = (g_mask[row] != 0) ? o : 0.f;
    }
}

// ---------- launch ----------
extern "C" void kernel_launch(void* const* d_in, const int* in_sizes, int n_in,
                              void* d_out, int out_size)
{
    (void)in_sizes; (void)n_in; (void)out_size;
    const float* h    = (const float*)d_in[0];
    const float* ef   = (const float*)d_in[1];
    const unsigned char* maskraw = (const unsigned char*)d_in[2];
    const float* We1  = (const float*)d_in[3];
    const float* be1  = (const float*)d_in[4];
    const float* We2  = (const float*)d_in[5];
    const float* be2  = (const float*)d_in[6];
    const float* Wa1  = (const float*)d_in[7];
    const float* ba1  = (const float*)d_in[8];
    const float* Wa2  = (const float*)d_in[9];
    const float* ba2  = (const float*)d_in[10];
    const float* Wm1  = (const float*)d_in[11];
    const float* bm1  = (const float*)d_in[12];
    const float* Wm2  = (const float*)d_in[13];
    const float* bm2  = (const float*)d_in[14];
    const float* Wo1  = (const float*)d_in[15];
    const float* bo1  = (const float*)d_in[16];
    const float* Wo2  = (const float*)d_in[17];
    const float* bo2  = (const float*)d_in[18];
    const float* gamma= (const float*)d_in[19];
    const float* beta = (const float*)d_in[20];

    cudaFuncSetAttribute(edge_kernel, cudaFuncAttributeMaxDynamicSharedMemorySize, SMEM_TOTAL);

    prep_kernel<<<NROW/16 + Hd/2 + 1, 256>>>(h, maskraw, We1, We2, Wa1, Wm1);
    edge_kernel<<<dim3(4, Ld, Bd), 128, SMEM_TOTAL>>>(ef, be1, be2, ba1, ba2, Wa2, bm1);
    final_kernel<<<NROW/16, 256>>>(h, Wm2, bm2, Wo1, bo1, Wo2, bo2, gamma, beta, (float*)d_out);
}

// round 17
// speedup vs baseline: 1.0219x; 1.0219x over previous
#include <cuda_runtime.h>
#include <cuda_bf16.h>
#include <math.h>
#include <stdint.h>

#define Hd 128
#define Ed 32
#define Ld 256
#define Bd 8
#define NROW (Bd*Ld)

// ---------- helpers ----------
__device__ __forceinline__ uint32_t smem_u32(const void* p){
    uint32_t a;
    asm("{ .reg .u64 t; cvta.to.shared.u64 t, %1; cvt.u32.u64 %0, t; }" : "=r"(a) : "l"(p));
    return a;
}
__device__ __forceinline__ void ldsm4(uint32_t& r0,uint32_t& r1,uint32_t& r2,uint32_t& r3,uint32_t a){
    asm volatile("ldmatrix.sync.aligned.m8n8.x4.shared.b16 {%0,%1,%2,%3}, [%4];"
        : "=r"(r0),"=r"(r1),"=r"(r2),"=r"(r3) : "r"(a));
}
__device__ __forceinline__ void mma16816(float* c, const uint32_t* a, const uint32_t* b){
    asm volatile("mma.sync.aligned.m16n8k16.row.col.f32.bf16.bf16.f32 "
        "{%0,%1,%2,%3}, {%4,%5,%6,%7}, {%8,%9}, {%0,%1,%2,%3};"
        : "+f"(c[0]),"+f"(c[1]),"+f"(c[2]),"+f"(c[3])
        : "r"(a[0]),"r"(a[1]),"r"(a[2]),"r"(a[3]), "r"(b[0]),"r"(b[1]));
}
__device__ __forceinline__ float tanh_fast(float x){
    float y; asm("tanh.approx.f32 %0, %1;" : "=f"(y) : "f"(x)); return y;
}
__device__ __forceinline__ unsigned short bf16raw(float x){
    __nv_bfloat16 b = __float2bfloat16(x);
    return *reinterpret_cast<unsigned short*>(&b);
}
__device__ __forceinline__ float bf16val(unsigned short u){
    __nv_bfloat16 b = *reinterpret_cast<__nv_bfloat16*>(&u);
    return __bfloat162float(b);
}
// fast 2-way split: hi = truncated-bf16 pair (pure byte-perm), lo = rn-bf16 of residual
__device__ __forceinline__ void split2(float v0, float v1, uint32_t& hi, uint32_t& lo){
    uint32_t u0 = __float_as_uint(v0), u1 = __float_as_uint(v1);
    hi = __byte_perm(u0, u1, 0x7632);
    float h0 = __uint_as_float(u0 & 0xFFFF0000u);
    float h1 = __uint_as_float(u1 & 0xFFFF0000u);
    asm("cvt.rn.bf16x2.f32 %0, %1, %2;" : "=r"(lo) : "f"(v1 - h1), "f"(v0 - h0));
}
// swizzled byte offset, 256B-stride tile (A): row r, byte col c2 (<256)
__device__ __forceinline__ uint32_t sw(int r, int c2){
    return (uint32_t)(r*256 + (c2 ^ ((r & 7) << 4)));
}
#define CP_ASYNC16(dst, src) asm volatile("cp.async.ca.shared.global [%0], [%1], 16;" :: "r"(dst), "l"(src))
#define CP_COMMIT()          asm volatile("cp.async.commit_group;" ::: "memory")
#define CP_WAIT0()           asm volatile("cp.async.wait_group 0;" ::: "memory")

// ---------- scratch ----------
__device__ float g_asrc[NROW*Hd];
__device__ float g_adst[NROW*Hd];
__device__ float g_hWm[NROW*Hd];
__device__ float g_V[NROW*4*Hd];
__device__ float g_S[NROW*4];
__device__ unsigned char g_mask[NROW];
__device__ int g_jcnt[Bd];
__device__ int g_jidx[Bd][Ld];
// weights packed as the exact smem image: [half(2)][hi 16KB | lo 16KB], rows n (128B stride,
// swizzled). [0]=We1 (half0 only), [1]=We2, [2]=Wae, [3]=Wme
__device__ __align__(16) unsigned short g_W[4][32768];

// ---------- setup body (256 threads): mask canonicalize + j-compaction ----------
__device__ void setup_body(const unsigned char* __restrict__ p, int t, int* sInts /* >= 10 */)
{
    int* fF = sInts; int* fB = sInts + 1; int* wcnt = sInts + 2;   // wcnt[8]
    int wid = t >> 5, lane = t & 31;
    if (t == 0) { *fF = 0; *fB = 0; }
    __syncthreads();
    for (int i = t; i < NROW; i += 256) {
        unsigned char v = p[i];
        if (v > 1) atomicOr(fF, 1);
        else if (v != 0 && (i & 3) != 0) atomicOr(fB, 1);
    }
    __syncthreads();
    bool isF = *fF != 0, isB = *fB != 0;
    for (int r = t; r < NROW; r += 256) {
        unsigned char m;
        if (isF)      m = (((const float*)p)[r] != 0.f) ? 1 : 0;
        else if (isB) m = p[r] ? 1 : 0;
        else          m = p[4*r] ? 1 : 0;
        g_mask[r] = m;
    }
    __syncthreads();
    for (int b = 0; b < Bd; b++) {
        int valid = (g_mask[b*Ld + t] != 0) ? 1 : 0;
        unsigned bal = __ballot_sync(0xffffffffu, valid);
        if (lane == 0) wcnt[wid] = __popc(bal);
        __syncthreads();
        int off = 0;
        #pragma unroll
        for (int w = 0; w < 8; w++) if (w < wid) off += wcnt[w];
        int pre = __popc(bal & ((1u << lane) - 1u));
        if (valid) g_jidx[b][off + pre] = t;
        if (t == 0) {
            int tot = 0;
            #pragma unroll
            for (int w = 0; w < 8; w++) tot += wcnt[w];
            g_jcnt[b] = tot;
        }
        __syncthreads();
    }
}

// ---------- kernel 1: smem-staged precompute + weight prep + setup (256 thr) ----------
// dynamic smem layout (floats): sh[16*128] | sW[128*128] | sPart[2*16*128]
#define PREP_SMEM_FLOATS (2048 + 16384 + 4096)
__global__ void __launch_bounds__(256)
prep_kernel(const float* __restrict__ h, const unsigned char* __restrict__ maskraw,
            const float* __restrict__ We1, const float* __restrict__ We2,
            const float* __restrict__ Wa1, const float* __restrict__ Wm1)
{
    extern __shared__ float dsm[];
    int t = threadIdx.x;   // 256
    if (blockIdx.x < NROW/16) {
        float* sh    = dsm;            // 16 x 128
        float* sW    = dsm + 2048;     // 128 x 128 (one full weight matrix)
        float* sPart = dsm + 2048 + 16384;  // 2 x 16 x 128
        const uint32_t sWa = smem_u32(sW);
        int r0 = blockIdx.x * 16;
        int n = t & 127, kh = t >> 7;
        const int kb = kh * 64;
        for (int i = t; i < 16*Hd; i += 256) {
            int r = i >> 7, c = i & 127;
            sh[r*Hd + c] = h[(r0 + r)*Hd + c];
        }
        const float* Wsrc[3] = { Wa1, Wa1 + Hd*Hd, Wm1 };
        float* gout[3] = { g_asrc, g_adst, g_hWm };
        for (int pass = 0; pass < 3; pass++) {
            // bulk-stage the 64 KB weight matrix (contiguous) into smem
            {
                const char* src = (const char*)Wsrc[pass];
                #pragma unroll
                for (int i = 0; i < 16; i++) {
                    int x = (t + i*256) * 16;
                    CP_ASYNC16(sWa + (uint32_t)x, src + x);
                }
                CP_COMMIT();
            }
            CP_WAIT0();
            __syncthreads();               // sW ready (and prior sPart reads done)
            float acc[16];
            #pragma unroll
            for (int r = 0; r < 16; r++) acc[r] = 0.f;
            #pragma unroll 8
            for (int k = kb; k < kb + 64; k++) {
                float wv = sW[k*Hd + n];
                #pragma unroll
                for (int r = 0; r < 16; r++) acc[r] = fmaf(sh[r*Hd + k], wv, acc[r]);
            }
            #pragma unroll
            for (int r = 0; r < 16; r++) sPart[(kh*16 + r)*Hd + n] = acc[r];
            __syncthreads();               // sPart ready; all sW reads done
            #pragma unroll
            for (int rr = 0; rr < 8; rr++) {
                int r = kh*8 + rr;
                gout[pass][(size_t)(r0 + r)*Hd + n] = sPart[r*Hd + n] + sPart[(16 + r)*Hd + n];
            }
            // next pass's copy (after CP_WAIT0+sync) is safe: sW reads finished at sync above
        }
    } else if (blockIdx.x < NROW/16 + Hd/2) {
        // ---- weight transpose+split+swizzle: 2 n-rows per block ----
        int n = (blockIdx.x - NROW/16)*2 + (t >> 7), k = t & 127;
        int half = k >> 6, kp = k & 63;
        uint32_t idx = (uint32_t)half*16384u + (uint32_t)n*64u
                     + ((((uint32_t)(kp*2)) ^ (uint32_t)((n & 7) << 4)) >> 1);
        if (k < Ed) {
            float w = We1[k*Hd + n];
            unsigned short hh = bf16raw(w);
            g_W[0][idx] = hh; g_W[0][idx + 8192] = bf16raw(w - bf16val(hh));
        }
        { float w = We2[k*Hd + n];        unsigned short hh=bf16raw(w); g_W[1][idx]=hh; g_W[1][idx+8192]=bf16raw(w-bf16val(hh)); }
        { float w = Wa1[(2*Hd+k)*Hd + n]; unsigned short hh=bf16raw(w); g_W[2][idx]=hh; g_W[2][idx+8192]=bf16raw(w-bf16val(hh)); }
        { float w = Wm1[(Hd+k)*Hd + n];   unsigned short hh=bf16raw(w); g_W[3][idx]=hh; g_W[3][idx+8192]=bf16raw(w-bf16val(hh)); }
    } else {
        setup_body(maskraw, t, (int*)dsm);
    }
}

// ---------- edge kernel smem layout (bytes) ----------
#define OFF_VECA 0
#define OFF_VECM 512
#define OFF_WA2  1024
#define OFF_BE1  1536
#define OFF_BE2  2048
#define OFF_SW   2560
#define OFF_RED  2816
#define OFF_VAGG 3328
#define OFF_JIDX 3840
#define OFF_AHI  4096
#define OFF_ALO  (OFF_AHI + 16384)
#define OFF_B0   (OFF_ALO + 16384)    // 32 KB: one K-half (hi 16K | lo 16K)
#define OFF_B1   (OFF_B0 + 32768)
#define SMEM_TOTAL (OFF_B1 + 32768)   // 102400

// async-copy one 32 KB weight K-half into a B buffer
__device__ __forceinline__ void cpasyncB(uint32_t dst, const unsigned short* src, int tid){
    const char* s = (const char*)src;
    #pragma unroll
    for (int i = 0; i < 16; i++) {
        int x = (tid + i*128) * 16;
        CP_ASYNC16(dst + (uint32_t)x, s + x);
    }
    CP_COMMIT();
}

// 3-pass bf16-split GEMM over one K-half. A: 256B-stride swizzled (full K=128);
// B: 128B-stride swizzled half-buffer, hi at bB, lo at bB+16384. kA0 = A k-elem offset.
template<int KS>
__device__ __forceinline__ void gemm_half(float C[2][8][4],
                                          uint32_t aHi, uint32_t aLo, uint32_t bB,
                                          int m0, int n0, int lane, int kA0)
{
    const int ra = m0 + (lane & 15);
    const uint32_t abase = (uint32_t)ra*256, axor = (uint32_t)((ra & 7) << 4);
    const int ac0 = (lane >> 4) * 16;
    const int rb = n0 + (lane & 7) + ((lane & 16) ? 8 : 0);
    const uint32_t bbase = (uint32_t)rb*128, bxor = (uint32_t)((rb & 7) << 4);
    const int bc0 = (lane & 8) ? 16 : 0;
    #pragma unroll
    for (int ks = 0; ks < KS; ks++) {
        const uint32_t ao = (uint32_t)(ac0 + kA0*2 + ks*32) ^ axor;
        const uint32_t bo = (uint32_t)(bc0 + ks*32) ^ bxor;
        uint32_t aH[2][4], aL[2][4], bH[8][2], bL[8][2];
        #pragma unroll
        for (int im = 0; im < 2; im++) {
            uint32_t ad = abase + (uint32_t)(im*16*256) + ao;
            ldsm4(aH[im][0],aH[im][1],aH[im][2],aH[im][3], aHi + ad);
            ldsm4(aL[im][0],aL[im][1],aL[im][2],aL[im][3], aLo + ad);
        }
        #pragma unroll
        for (int ib = 0; ib < 4; ib++) {
            uint32_t bd = bbase + (uint32_t)(ib*16*128) + bo;
            ldsm4(bH[2*ib][0],bH[2*ib][1],bH[2*ib+1][0],bH[2*ib+1][1], bB + bd);
            ldsm4(bL[2*ib][0],bL[2*ib][1],bL[2*ib+1][0],bL[2*ib+1][1], bB + 16384 + bd);
        }
        #pragma unroll
        for (int im = 0; im < 2; im++)
            #pragma unroll
            for (int in = 0; in < 8; in++) {
                mma16816(C[im][in], aH[im], bH[in]);
                mma16816(C[im][in], aH[im], bL[in]);
                mma16816(C[im][in], aL[im], bH[in]);
            }
    }
}

#define ZC() { _Pragma("unroll") for(int _i=0;_i<2;_i++) _Pragma("unroll") for(int _j=0;_j<8;_j++) _Pragma("unroll") for(int _k=0;_k<4;_k++) C[_i][_j][_k]=0.f; }

// epilogue: bias (+relu), split to bf16 hi/lo (truncation trick), store into A tiles
__device__ __forceinline__ void epi_store_A(float C[2][8][4], const float* __restrict__ bias,
                                            bool do_relu, unsigned char* smem,
                                            int m0, int n0, int lane)
{
    #pragma unroll
    for (int im = 0; im < 2; im++)
        #pragma unroll
        for (int in = 0; in < 8; in++) {
            int n = n0 + in*8 + 2*(lane & 3);
            float b0 = bias[n], b1 = bias[n+1];
            #pragma unroll
            for (int hh = 0; hh < 2; hh++) {
                int m = m0 + im*16 + hh*8 + (lane >> 2);
                float v0 = C[im][in][2*hh]   + b0;
                float v1 = C[im][in][2*hh+1] + b1;
                if (do_relu) { v0 = fmaxf(v0, 0.f); v1 = fmaxf(v1, 0.f); }
                uint32_t hi, lo;
                split2(v0, v1, hi, lo);
                uint32_t off = sw(m, n*2);
                *(uint32_t*)(smem + OFF_AHI + off) = hi;
                *(uint32_t*)(smem + OFF_ALO + off) = lo;
            }
        }
}

// block: (jt, i, b) -> 64 compacted j's (jidx[j0..j0+63]) of row (b,i); M=64, N=128
__global__ void __launch_bounds__(128, 2)
edge_kernel(const float* __restrict__ ef,
            const float* __restrict__ be1, const float* __restrict__ be2,
            const float* __restrict__ ba1, const float* __restrict__ ba2,
            const float* __restrict__ Wa2, const float* __restrict__ bm1)
{
    extern __shared__ unsigned char smem[];
    const uint32_t sb = smem_u32(smem);
    const int tid = threadIdx.x, lane = tid & 31, wid = tid >> 5;
    const int wm = wid >> 1, wn = wid & 1;
    const int m0 = wm*32, n0 = wn*64;
    const int jt = blockIdx.x, i = blockIdx.y, b = blockIdx.z;
    const int row = b*Ld + i;
    const int j0  = jt*64;
    const int cnt = g_jcnt[b];

    // ---- early exit: masked center row, or j-tile beyond valid count (no writes) ----
    if (g_mask[row] == 0 || j0 >= cnt) return;

    float* sVA  = (float*)(smem + OFF_VECA);
    float* sVM  = (float*)(smem + OFF_VECM);
    float* sW2  = (float*)(smem + OFF_WA2);
    float* sB1  = (float*)(smem + OFF_BE1);
    float* sB2  = (float*)(smem + OFF_BE2);
    float* swv  = (float*)(smem + OFF_SW);
    float* red  = (float*)(smem + OFF_RED);
    float* sVag = (float*)(smem + OFF_VAGG);
    int*   sJ   = (int*)(smem + OFF_JIDX);
    const uint32_t aHi = sb + OFF_AHI, aLo = sb + OFF_ALO;
    const uint32_t B0 = sb + OFF_B0, B1 = sb + OFF_B1;

    // prefetch We1 half0 immediately (overlaps all scalar staging below)
    cpasyncB(B0, g_W[0], tid);

    sVA[tid] = g_asrc[row*Hd + tid] + __ldg(&ba1[tid]);
    sVM[tid] = g_hWm [row*Hd + tid] + __ldg(&bm1[tid]);
    sW2[tid] = __ldg(&Wa2[tid]);
    sB1[tid] = __ldg(&be1[tid]);
    sB2[tid] = __ldg(&be2[tid]);
    sVag[tid] = 0.f;
    if (tid < 64) {
        int jj = j0 + tid;
        sJ[tid] = (jj < cnt) ? g_jidx[b][jj] : g_jidx[b][0];
    }

    // stage EF (64 gathered rows x 32) split hi/lo into A tiles
    {
        int r = tid >> 1, half = tid & 1;
        int jj = j0 + r;
        int jv = (jj < cnt) ? __ldg(&g_jidx[b][jj]) : __ldg(&g_jidx[b][0]);
        const float* src = ef + (((size_t)row*Ld) + jv)*Ed + half*16;
        uint32_t hi[8], lo[8];
        #pragma unroll
        for (int g = 0; g < 4; g++) {
            float4 v = *(const float4*)(src + g*4);
            split2(v.x, v.y, hi[2*g],   lo[2*g]);
            split2(v.z, v.w, hi[2*g+1], lo[2*g+1]);
        }
        uint32_t o0 = sw(r, half*32), o1 = sw(r, half*32 + 16);
        *(uint4*)(smem + OFF_AHI + o0) = make_uint4(hi[0],hi[1],hi[2],hi[3]);
        *(uint4*)(smem + OFF_AHI + o1) = make_uint4(hi[4],hi[5],hi[6],hi[7]);
        *(uint4*)(smem + OFF_ALO + o0) = make_uint4(lo[0],lo[1],lo[2],lo[3]);
        *(uint4*)(smem + OFF_ALO + o1) = make_uint4(lo[4],lo[5],lo[6],lo[7]);
    }
    CP_WAIT0();
    __syncthreads();

    float C[2][8][4];

    // ---- G1: T = relu(EF @ We1 + be1) (K=32, B0) ----
    ZC();
    gemm_half<2>(C, aHi, aLo, B0, m0, n0, lane, 0);
    cpasyncB(B1, g_W[1], tid);                 // We2 h0 -> B1 (B1 unused yet)
    __syncthreads();                           // all warps done reading A (G1)
    epi_store_A(C, sB1, true, smem, m0, n0, lane);
    CP_WAIT0();
    __syncthreads();                           // T visible + B1 ready

    // ---- G2: EH = T @ We2 + be2 (two K-halves) ----
    ZC();
    gemm_half<4>(C, aHi, aLo, B1, m0, n0, lane, 0);
    cpasyncB(B0, g_W[1] + 16384, tid);         // We2 h1 -> B0 (B0 free since pre-epi sync)
    CP_WAIT0();
    __syncthreads();                           // B0 ready; all warps done with B1
    gemm_half<4>(C, aHi, aLo, B0, m0, n0, lane, 64);
    cpasyncB(B1, g_W[2], tid);                 // Wae h0 -> B1
    __syncthreads();                           // all warps done reading A (G2)
    epi_store_A(C, sB2, false, smem, m0, n0, lane);
    CP_WAIT0();
    __syncthreads();                           // EH visible + B1 ready

    // ---- G3a: U = EH @ Wae ----
    ZC();
    gemm_half<4>(C, aHi, aLo, B1, m0, n0, lane, 0);
    cpasyncB(B0, g_W[2] + 16384, tid);         // Wae h1 -> B0
    CP_WAIT0();
    __syncthreads();
    gemm_half<4>(C, aHi, aLo, B0, m0, n0, lane, 64);
    cpasyncB(B1, g_W[3], tid);                 // Wme h0 -> B1
    // attention epilogue (C regs are this thread's; no sync needed before use)
    {
        #pragma unroll
        for (int im = 0; im < 2; im++)
            #pragma unroll
            for (int hh = 0; hh < 2; hh++) {
                int m = m0 + im*16 + hh*8 + (lane >> 2);
                const float* ad = g_adst + (((size_t)b*Ld) + sJ[m])*Hd;
                float part = 0.f;
                #pragma unroll
                for (int in = 0; in < 8; in++) {
                    int n = n0 + in*8 + 2*(lane & 3);
                    float2 a2 = *(const float2*)(ad + n);
                    float u0 = C[im][in][2*hh]   + sVA[n]   + a2.x;
                    float u1 = C[im][in][2*hh+1] + sVA[n+1] + a2.y;
                    part = fmaf(tanh_fast(u0), sW2[n],   part);
                    part = fmaf(tanh_fast(u1), sW2[n+1], part);
                }
                part += __shfl_xor_sync(0xffffffffu, part, 1);
                part += __shfl_xor_sync(0xffffffffu, part, 2);
                if ((lane & 3) == 0) red[m*2 + wn] = part;
            }
    }
    __syncthreads();
    if (tid < 64) {
        float s = red[tid*2] + red[tid*2 + 1];
        float logit = (s + __ldg(&ba2[0])) * 0.08838834764831845f;
        bool valid = (j0 + tid) < cnt;         // compacted j's are all mask-valid
        swv[tid] = valid ? __expf(logit) : 0.f;
    }
    CP_WAIT0();
    __syncthreads();                           // B1 (Wme h0) ready + swv visible

    // ---- G3b: MPpre = EH @ Wme ----
    ZC();
    gemm_half<4>(C, aHi, aLo, B1, m0, n0, lane, 0);
    cpasyncB(B0, g_W[3] + 16384, tid);         // Wme h1 -> B0
    CP_WAIT0();
    __syncthreads();
    gemm_half<4>(C, aHi, aLo, B0, m0, n0, lane, 64);
    // message epilogue + weighted aggregation
    {
        float vacc[8][2];
        #pragma unroll
        for (int in = 0; in < 8; in++) { vacc[in][0] = 0.f; vacc[in][1] = 0.f; }
        #pragma unroll
        for (int im = 0; im < 2; im++)
            #pragma unroll
            for (int hh = 0; hh < 2; hh++) {
                int m = m0 + im*16 + hh*8 + (lane >> 2);
                float w = swv[m];
                #pragma unroll
                for (int in = 0; in < 8; in++) {
                    int n = n0 + in*8 + 2*(lane & 3);
                    vacc[in][0] = fmaf(w, fmaxf(C[im][in][2*hh]   + sVM[n],   0.f), vacc[in][0]);
                    vacc[in][1] = fmaf(w, fmaxf(C[im][in][2*hh+1] + sVM[n+1], 0.f), vacc[in][1]);
                }
            }
        #pragma unroll
        for (int in = 0; in < 8; in++)
            #pragma unroll
            for (int c = 0; c < 2; c++) {
                float v = vacc[in][c];
                v += __shfl_xor_sync(0xffffffffu, v, 4);
                v += __shfl_xor_sync(0xffffffffu, v, 8);
                v += __shfl_xor_sync(0xffffffffu, v, 16);
                if (lane < 4) atomicAdd(&sVag[n0 + in*8 + 2*lane + c], v);
            }
    }
    __syncthreads();
    g_V[((size_t)row*4 + jt)*Hd + tid] = sVag[tid];
    if (tid < 64) {
        float wv = swv[tid];
        #pragma unroll
        for (int o = 16; o > 0; o >>= 1) wv += __shfl_xor_sync(0xffffffffu, wv, o);
        if ((tid & 31) == 0) red[tid >> 5] = wv;
    }
    __syncthreads();
    if (tid == 0) g_S[row*4 + jt] = red[0] + red[1];
}

// ---------- final kernel v3: 16 rows/block, 256 threads, k-split halves ----------
__global__ void __launch_bounds__(256)
final_kernel(const float* __restrict__ h,
             const float* __restrict__ Wm2, const float* __restrict__ bm2,
             const float* __restrict__ Wo1, const float* __restrict__ bo1,
             const float* __restrict__ Wo2, const float* __restrict__ bo2,
             const float* __restrict__ gamma, const float* __restrict__ beta,
             float* __restrict__ out)
{
    int t = threadIdx.x;
    int n = t & 127, kh = t >> 7;        // kh in {0,1}; k range [kh*64, kh*64+64)
    int r0 = blockIdx.x * 16;            // 128 blocks
    int b = r0 >> 8;
    __shared__ float sA[16][Hd];         // agg; reused as sP after stage 1
    __shared__ float sH[16][Hd];
    __shared__ float sX2[16][Hd];
    __shared__ float sPart[2][16][Hd];
    __shared__ float sMu[16], sRs[16];
    float* sP = &sA[0][0];               // alias: sA dead after stage-1 partials

    int cnt = g_jcnt[b];
    int ntiles = (cnt + 63) >> 6;
    for (int i = t; i < 16*Hd; i += 256) {
        int r = i >> 7, c = i & 127;
        int row = r0 + r;
        sH[r][c] = h[row*Hd + c];
        float a = 0.f;
        if (g_mask[row]) {
            float v = 0.f, S = 0.f;
            for (int jt = 0; jt < ntiles; jt++) {
                v += g_V[((size_t)row*4 + jt)*Hd + c];
                S += g_S[row*4 + jt];
            }
            a = v / S;
        }
        sA[r][c] = a;
    }
    __syncthreads();

    float acc[16];
    const int kb = kh*64;
    // ---- stage 1: X2 = agg @ Wm2 + bm2 ----
    #pragma unroll
    for (int r = 0; r < 16; r++) acc[r] = 0.f;
    #pragma unroll 8
    for (int k = kb; k < kb + 64; k++) {
        float wv = __ldg(&Wm2[k*Hd + n]);
        #pragma unroll
        for (int r = 0; r < 16; r++) acc[r] = fmaf(sA[r][k], wv, acc[r]);
    }
    #pragma unroll
    for (int r = 0; r < 16; r++) sPart[kh][r][n] = acc[r];
    __syncthreads();
    {
        float bm = __ldg(&bm2[n]);
        #pragma unroll
        for (int rr = 0; rr < 8; rr++) {
            int r = kh*8 + rr;
            sX2[r][n] = bm + sPart[0][r][n] + sPart[1][r][n];
        }
    }
    __syncthreads();
    // ---- stage 2: P = relu(h@Wo1[:H] + X2@Wo1[H:] + bo1)  (sP aliases sA) ----
    #pragma unroll
    for (int r = 0; r < 16; r++) acc[r] = 0.f;
    #pragma unroll 4
    for (int k = kb; k < kb + 64; k++) {
        float w1 = __ldg(&Wo1[k*Hd + n]);
        float w2 = __ldg(&Wo1[(Hd + k)*Hd + n]);
        #pragma unroll
        for (int r = 0; r < 16; r++) {
            acc[r] = fmaf(sH[r][k],  w1, acc[r]);
            acc[r] = fmaf(sX2[r][k], w2, acc[r]);
        }
    }
    __syncthreads();                      // all reads of sA (stage-1 operand) complete
    #pragma unroll
    for (int r = 0; r < 16; r++) sPart[kh][r][n] = acc[r];
    __syncthreads();
    {
        float b1 = __ldg(&bo1[n]);
        #pragma unroll
        for (int rr = 0; rr < 8; rr++) {
            int r = kh*8 + rr;
            sP[r*Hd + n] = fmaxf(b1 + sPart[0][r][n] + sPart[1][r][n], 0.f);
        }
    }
    __syncthreads();
    // ---- stage 3: res = h + P@Wo2 + bo2 -> sX2 ----
    #pragma unroll
    for (int r = 0; r < 16; r++) acc[r] = 0.f;
    #pragma unroll 8
    for (int k = kb; k < kb + 64; k++) {
        float wv = __ldg(&Wo2[k*Hd + n]);
        #pragma unroll
        for (int r = 0; r < 16; r++) acc[r] = fmaf(sP[r*Hd + k], wv, acc[r]);
    }
    #pragma unroll
    for (int r = 0; r < 16; r++) sPart[kh][r][n] = acc[r];
    __syncthreads();
    {
        float b2 = __ldg(&bo2[n]);
        #pragma unroll
        for (int rr = 0; rr < 8; rr++) {
            int r = kh*8 + rr;
            sX2[r][n] = sH[r][n] + b2 + sPart[0][r][n] + sPart[1][r][n];
        }
    }
    __syncthreads();
    // ---- LayerNorm: 8 warps, 2 rows each ----
    {
        int w = t >> 5, lane = t & 31;
        #pragma unroll
        for (int g = 0; g < 2; g++) {
            int r = w*2 + g;
            float s = 0.f, q = 0.f;
            #pragma unroll
            for (int x = 0; x < 4; x++) {
                float v = sX2[r][lane + x*32];
                s += v; q = fmaf(v, v, q);
            }
            #pragma unroll
            for (int o = 16; o > 0; o >>= 1) {
                s += __shfl_xor_sync(0xffffffffu, s, o);
                q += __shfl_xor_sync(0xffffffffu, q, o);
            }
            if (lane == 0) {
                float mu = s * (1.f/128.f);
                float var = q * (1.f/128.f) - mu*mu;
                sMu[r] = mu; sRs[r] = rsqrtf(var + 1e-5f);
            }
        }
    }
    __syncthreads();
    for (int i = t; i < 16*Hd; i += 256) {
        int r = i >> 7, c = i & 127;
        int row = r0 + r;
        float o = (sX2[r][c] - sMu[r]) * sRs[r] * __ldg(&gamma[c]) + __ldg(&beta[c]);
        out[row*Hd + c] = (g_mask[row] != 0) ? o : 0.f;
    }
}

// ---------- launch ----------
extern "C" void kernel_launch(void* const* d_in, const int* in_sizes, int n_in,
                              void* d_out, int out_size)
{
    (void)in_sizes; (void)n_in; (void)out_size;
    const float* h    = (const float*)d_in[0];
    const float* ef   = (const float*)d_in[1];
    const unsigned char* maskraw = (const unsigned char*)d_in[2];
    const float* We1  = (const float*)d_in[3];
    const float* be1  = (const float*)d_in[4];
    const float* We2  = (const float*)d_in[5];
    const float* be2  = (const float*)d_in[6];
    const float* Wa1  = (const float*)d_in[7];
    const float* ba1  = (const float*)d_in[8];
    const float* Wa2  = (const float*)d_in[9];
    const float* ba2  = (const float*)d_in[10];
    const float* Wm1  = (const float*)d_in[11];
    const float* bm1  = (const float*)d_in[12];
    const float* Wm2  = (const float*)d_in[13];
    const float* bm2  = (const float*)d_in[14];
    const float* Wo1  = (const float*)d_in[15];
    const float* bo1  = (const float*)d_in[16];
    const float* Wo2  = (const float*)d_in[17];
    const float* bo2  = (const float*)d_in[18];
    const float* gamma= (const float*)d_in[19];
    const float* beta = (const float*)d_in[20];

    const int prepSmem = PREP_SMEM_FLOATS * (int)sizeof(float);  // 90112
    cudaFuncSetAttribute(prep_kernel, cudaFuncAttributeMaxDynamicSharedMemorySize, prepSmem);
    cudaFuncSetAttribute(edge_kernel, cudaFuncAttributeMaxDynamicSharedMemorySize, SMEM_TOTAL);

    prep_kernel<<<NROW/16 + Hd/2 + 1, 256, prepSmem>>>(h, maskraw, We1, We2, Wa1, Wm1);
    edge_kernel<<<dim3(4, Ld, Bd), 128, SMEM_TOTAL>>>(ef, be1, be2, ba1, ba2, Wa2, bm1);
    final_kernel<<<NROW/16, 256>>>(h, Wm2, bm2, Wo1, bo1, Wo2, bo2, gamma, beta, (float*)d_out);
}